// round 1
// baseline (speedup 1.0000x reference)
#include <cuda_runtime.h>
#include <math.h>

// Problem constants (b=4, c=256, h=w=64)
#define BATCH 4
#define CDIM  256
#define NSP   4096            // h*w
#define BN2   16777216        // NSP*NSP
#define TOPK3 3

// Scratch (device globals; no allocation allowed)
__device__ float g_inv_np[BATCH * NSP];
__device__ float g_inv_nq[BATCH * NSP];
__device__ float g_rowsum[BATCH * NSP];
__device__ float g_colsum[BATCH * NSP];

// ---------------------------------------------------------------------------
// Kernel 0: zero the sum accumulators (must be re-zeroed every graph replay)
// ---------------------------------------------------------------------------
__global__ void zero_sums_kernel() {
    int i = blockIdx.x * 256 + threadIdx.x;   // 64 blocks * 256 = 16384
    g_rowsum[i] = 0.0f;
    g_colsum[i] = 0.0f;
}

// ---------------------------------------------------------------------------
// Kernel 1: inverse L2 norms over channel dim.
// xp layout: [b][c][hw], hw contiguous -> coalesced loads.
// ---------------------------------------------------------------------------
__global__ void norms_kernel(const float* __restrict__ xp,
                             const float* __restrict__ xq) {
    int idx = blockIdx.x * 256 + threadIdx.x;   // 0 .. BATCH*NSP-1 (grid.x=64)
    const float* src = (blockIdx.y == 0) ? xp : xq;
    float*       dst = (blockIdx.y == 0) ? g_inv_np : g_inv_nq;
    int b = idx >> 12;
    int i = idx & (NSP - 1);
    const float* p = src + (size_t)b * CDIM * NSP + i;
    float s = 0.0f;
    #pragma unroll 8
    for (int c = 0; c < CDIM; c++) {
        float v = p[(size_t)c * NSP];
        s = fmaf(v, v, s);
    }
    float n = sqrtf(s);
    dst[idx] = 1.0f / fmaxf(n, 1e-12f);
}

// ---------------------------------------------------------------------------
// Kernel 2: fused GEMM + normalize + alpha + exp, and row/col sum accumulation.
// Both operands are [K=256][N=4096] with the MN dim contiguous ("TN" SGEMM):
// no transpose needed, all global loads are float4-coalesced.
// Tile: 128x128x16, 256 threads, 8x8 accum per thread.
// Writes e = exp(s) into the xc_o_q slot of d_out.
// ---------------------------------------------------------------------------
__global__ __launch_bounds__(256)
void gemm_exp_kernel(const float* __restrict__ xp,
                     const float* __restrict__ xq,
                     const float* __restrict__ alpha_p,
                     float* __restrict__ out_e) {
    __shared__ float As[16][128];
    __shared__ float Bs[16][128];
    __shared__ float srow[128];
    __shared__ float scol[128];

    const int b  = blockIdx.z;
    const int i0 = blockIdx.y * 128;
    const int j0 = blockIdx.x * 128;
    const int t  = threadIdx.x;
    const int tx = t & 15;
    const int ty = t >> 4;

    const float* A = xp + (size_t)b * CDIM * NSP;   // [K][M]
    const float* B = xq + (size_t)b * CDIM * NSP;   // [K][N]

    float acc[8][8];
    #pragma unroll
    for (int r = 0; r < 8; r++)
        #pragma unroll
        for (int c = 0; c < 8; c++) acc[r][c] = 0.0f;

    for (int k0 = 0; k0 < CDIM; k0 += 16) {
        // Load 16x128 tiles of A and B (512 float4 each; 2 per thread)
        #pragma unroll
        for (int u = 0; u < 2; u++) {
            int f  = t + u * 256;
            int kk = f >> 5;            // 0..15
            int m4 = (f & 31) << 2;     // 0,4,...,124
            *reinterpret_cast<float4*>(&As[kk][m4]) =
                *reinterpret_cast<const float4*>(A + (size_t)(k0 + kk) * NSP + i0 + m4);
            *reinterpret_cast<float4*>(&Bs[kk][m4]) =
                *reinterpret_cast<const float4*>(B + (size_t)(k0 + kk) * NSP + j0 + m4);
        }
        __syncthreads();
        #pragma unroll
        for (int kk = 0; kk < 16; kk++) {
            float a[8], bb[8];
            #pragma unroll
            for (int r = 0; r < 8; r++) a[r]  = As[kk][ty * 8 + r];
            #pragma unroll
            for (int c = 0; c < 8; c++) bb[c] = Bs[kk][tx * 8 + c];
            #pragma unroll
            for (int r = 0; r < 8; r++)
                #pragma unroll
                for (int c = 0; c < 8; c++)
                    acc[r][c] = fmaf(a[r], bb[c], acc[r][c]);
        }
        __syncthreads();
    }

    // ---- epilogue: s = alpha * dot * inv_np[i] * inv_nq[j]; e = exp(s) ----
    if (t < 128) { srow[t] = 0.0f; scol[t] = 0.0f; }
    __syncthreads();

    const float alpha = __ldg(alpha_p);
    float rsc[8], csc[8];
    #pragma unroll
    for (int r = 0; r < 8; r++) rsc[r] = g_inv_np[b * NSP + i0 + ty * 8 + r] * alpha;
    #pragma unroll
    for (int c = 0; c < 8; c++) csc[c] = g_inv_nq[b * NSP + j0 + tx * 8 + c];

    float cpart[8] = {0, 0, 0, 0, 0, 0, 0, 0};
    const size_t obase = (size_t)b * BN2;
    #pragma unroll
    for (int r = 0; r < 8; r++) {
        float ev[8];
        float rp = 0.0f;
        #pragma unroll
        for (int c = 0; c < 8; c++) {
            float e = expf(acc[r][c] * rsc[r] * csc[c]);
            ev[c] = e;
            rp += e;
            cpart[c] += e;
        }
        float* orow = out_e + obase + (size_t)(i0 + ty * 8 + r) * NSP + j0 + tx * 8;
        *reinterpret_cast<float4*>(orow)     = make_float4(ev[0], ev[1], ev[2], ev[3]);
        *reinterpret_cast<float4*>(orow + 4) = make_float4(ev[4], ev[5], ev[6], ev[7]);
        atomicAdd(&srow[ty * 8 + r], rp);
    }
    #pragma unroll
    for (int c = 0; c < 8; c++) atomicAdd(&scol[tx * 8 + c], cpart[c]);
    __syncthreads();
    if (t < 128) {
        atomicAdd(&g_rowsum[b * NSP + i0 + t], srow[t]);
        atomicAdd(&g_colsum[b * NSP + j0 + t], scol[t]);
    }
}

// ---------------------------------------------------------------------------
// top-3 helpers
// ---------------------------------------------------------------------------
__device__ __forceinline__ void top3_push(float v, float& v0, float& v1, float& v2) {
    if (v > v2) {
        if (v > v1) {
            v2 = v1;
            if (v > v0) { v1 = v0; v0 = v; } else { v1 = v; }
        } else {
            v2 = v;
        }
    }
}

__device__ __forceinline__ void warp_reduce_top3(float& v0, float& v1, float& v2) {
    #pragma unroll
    for (int off = 16; off > 0; off >>= 1) {
        float u0 = __shfl_down_sync(0xFFFFFFFFu, v0, off);
        float u1 = __shfl_down_sync(0xFFFFFFFFu, v1, off);
        float u2 = __shfl_down_sync(0xFFFFFFFFu, v2, off);
        top3_push(u0, v0, v1, v2);
        top3_push(u1, v0, v1, v2);
        top3_push(u2, v0, v1, v2);
    }
}

// ---------------------------------------------------------------------------
// Kernel 3: row pass. In place: e -> x_c = e*e/(rowsum_i*colsum_j).
// One warp per row (8 rows / block), fused row top-3 -> valp.
// ---------------------------------------------------------------------------
__global__ __launch_bounds__(256)
void rowpass_kernel(float* __restrict__ xcq, float* __restrict__ valp) {
    __shared__ float sinvc[NSP];   // 16 KB: 1/colsum for this batch
    const int b = blockIdx.y;
    const int t = threadIdx.x;
    for (int j = t; j < NSP; j += 256)
        sinvc[j] = 1.0f / g_colsum[b * NSP + j];
    __syncthreads();

    const int w    = t >> 5;
    const int lane = t & 31;
    const int i    = blockIdx.x * 8 + w;
    const float invr = 1.0f / g_rowsum[b * NSP + i];
    float* row = xcq + (size_t)b * BN2 + (size_t)i * NSP;

    float v0 = -1e30f, v1 = -1e30f, v2 = -1e30f;
    for (int jb = lane * 4; jb < NSP; jb += 128) {
        float4 e  = *reinterpret_cast<float4*>(row + jb);
        float4 si = *reinterpret_cast<float4*>(&sinvc[jb]);
        float x0 = e.x * e.x * invr * si.x;
        float x1 = e.y * e.y * invr * si.y;
        float x2 = e.z * e.z * invr * si.z;
        float x3 = e.w * e.w * invr * si.w;
        *reinterpret_cast<float4*>(row + jb) = make_float4(x0, x1, x2, x3);
        top3_push(x0, v0, v1, v2);
        top3_push(x1, v0, v1, v2);
        top3_push(x2, v0, v1, v2);
        top3_push(x3, v0, v1, v2);
    }
    warp_reduce_top3(v0, v1, v2);
    if (lane == 0) {
        valp[b * 3 * NSP + 0 * NSP + i] = v0;
        valp[b * 3 * NSP + 1 * NSP + i] = v1;
        valp[b * 3 * NSP + 2 * NSP + i] = v2;
    }
}

// ---------------------------------------------------------------------------
// Kernel 4: column pass. Reads final x_c, writes xc_o_p = x_c^T via smem tile
// transpose, fused column top-3 -> valq. Block: 8 columns x full 4096 rows.
// ---------------------------------------------------------------------------
__global__ __launch_bounds__(256)
void colpass_kernel(const float* __restrict__ xcq,
                    float* __restrict__ xcp,
                    float* __restrict__ valq) {
    __shared__ float tile[32][9];
    const int b  = blockIdx.y;
    const int j0 = blockIdx.x << 3;
    const int t  = threadIdx.x;
    const float* src = xcq + (size_t)b * BN2;
    float*       dst = xcp + (size_t)b * BN2;

    const int li = t >> 3, lj = t & 7;    // load coords (32 rows x 8 cols)
    const int wj = t >> 5, wi = t & 31;   // write coords (8 cols x 32 rows)

    float v0 = -1e30f, v1 = -1e30f, v2 = -1e30f;
    for (int ic = 0; ic < NSP; ic += 32) {
        tile[li][lj] = src[(size_t)(ic + li) * NSP + j0 + lj];
        __syncthreads();
        float v = tile[wi][wj];
        dst[(size_t)(j0 + wj) * NSP + ic + wi] = v;
        top3_push(v, v0, v1, v2);
        __syncthreads();
    }
    warp_reduce_top3(v0, v1, v2);   // warp wj owns column j0+wj
    if (wi == 0) {
        int j = j0 + wj;
        valq[b * 3 * NSP + 0 * NSP + j] = v0;
        valq[b * 3 * NSP + 1 * NSP + j] = v1;
        valq[b * 3 * NSP + 2 * NSP + j] = v2;
    }
}

// ---------------------------------------------------------------------------
// Launch. Output layout: valp[4,3,64,64], valq[4,3,64,64],
//                        xc_o_p[4,4096,64,64], xc_o_q[4,4096,64,64]
// ---------------------------------------------------------------------------
extern "C" void kernel_launch(void* const* d_in, const int* in_sizes, int n_in,
                              void* d_out, int out_size) {
    const float* xp    = (const float*)d_in[0];
    const float* xq    = (const float*)d_in[1];
    const float* alpha = (const float*)d_in[2];

    float* valp = (float*)d_out;                 // 49152
    float* valq = valp + BATCH * 3 * NSP;        // 49152
    float* xcp  = valq + BATCH * 3 * NSP;        // 67108864
    float* xcq  = xcp + (size_t)BATCH * BN2;     // 67108864

    zero_sums_kernel<<<64, 256>>>();
    norms_kernel<<<dim3(64, 2), 256>>>(xp, xq);
    gemm_exp_kernel<<<dim3(32, 32, BATCH), 256>>>(xp, xq, alpha, xcq);
    rowpass_kernel<<<dim3(512, BATCH), 256>>>(xcq, valp);
    colpass_kernel<<<dim3(512, BATCH), 256>>>(xcq, xcp, valq);
}

// round 3
// speedup vs baseline: 2.0784x; 2.0784x over previous
#include <cuda_runtime.h>
#include <cuda_bf16.h>
#include <math.h>
#include <cstdint>

#define BATCH 4
#define CDIM  256
#define NSP   4096
#define BN2   16777216
#define KTOT  768          // [hi | lo | hi] x [hi | hi | lo]
#define NCHUNK 12          // K chunks of 64

// ---------------------------------------------------------------------------
// Device scratch
// ---------------------------------------------------------------------------
__device__ float g_rowsum[BATCH * NSP];
__device__ float g_colsum[BATCH * NSP];
__device__ __nv_bfloat16 g_P[(size_t)BATCH * NSP * KTOT];
__device__ __nv_bfloat16 g_Q[(size_t)BATCH * NSP * KTOT];

// ---------------------------------------------------------------------------
// PTX helpers (sm_80-compatible only: cp.async, ldmatrix, mma.sync)
// ---------------------------------------------------------------------------
__device__ __forceinline__ uint32_t smem_u32(const void* p) {
    uint32_t a;
    asm("{ .reg .u64 t; cvta.to.shared.u64 t, %1; cvt.u32.u64 %0, t; }"
        : "=r"(a) : "l"(p));
    return a;
}
__device__ __forceinline__ void cp16(uint32_t s, const void* g) {
    asm volatile("cp.async.cg.shared.global [%0], [%1], 16;" :: "r"(s), "l"(g));
}
__device__ __forceinline__ void cp_commit() {
    asm volatile("cp.async.commit_group;");
}
template <int N>
__device__ __forceinline__ void cp_wait() {
    asm volatile("cp.async.wait_group %0;" :: "n"(N));
}
__device__ __forceinline__ void ldmx4(uint32_t* r, uint32_t addr) {
    asm volatile("ldmatrix.sync.aligned.m8n8.x4.shared.b16 {%0,%1,%2,%3}, [%4];"
                 : "=r"(r[0]), "=r"(r[1]), "=r"(r[2]), "=r"(r[3]) : "r"(addr));
}
__device__ __forceinline__ void mma16816(float* d, const uint32_t* a, const uint32_t* b) {
    asm volatile(
        "mma.sync.aligned.m16n8k16.row.col.f32.bf16.bf16.f32 "
        "{%0,%1,%2,%3}, {%4,%5,%6,%7}, {%8,%9}, {%0,%1,%2,%3};"
        : "+f"(d[0]), "+f"(d[1]), "+f"(d[2]), "+f"(d[3])
        : "r"(a[0]), "r"(a[1]), "r"(a[2]), "r"(a[3]), "r"(b[0]), "r"(b[1]));
}

// ---------------------------------------------------------------------------
// Kernel 0: zero accumulators (re-zeroed every replay)
// ---------------------------------------------------------------------------
__global__ void zero_sums_kernel() {
    int i = blockIdx.x * 256 + threadIdx.x;
    g_rowsum[i] = 0.0f;
    g_colsum[i] = 0.0f;
}

// ---------------------------------------------------------------------------
// Kernel 1: prep — L2-normalize over channels, bf16 hi/lo split, transpose to
// K-major [m][768]:  P = [hi | lo | hi],  Q = [hi | hi | lo].
// ---------------------------------------------------------------------------
__global__ __launch_bounds__(256)
void prep_kernel(const float* __restrict__ xp, const float* __restrict__ xq) {
    __shared__ float tile[32][257];
    const int m0 = blockIdx.x * 32;
    const int b  = blockIdx.y;
    const int t  = threadIdx.x;
    const int w  = t >> 5, lane = t & 31;
    const bool isP = (blockIdx.z == 0);
    const float* src = isP ? xp : xq;
    __nv_bfloat16* dst = isP ? g_P : g_Q;

    #pragma unroll 8
    for (int it = 0; it < 32; it++) {
        int c = w + it * 8;
        tile[lane][c] = src[((size_t)b * CDIM + c) * NSP + m0 + lane];
    }
    __syncthreads();

    #pragma unroll
    for (int r = 0; r < 4; r++) {
        int row = w * 4 + r;
        float s = 0.0f;
        #pragma unroll
        for (int k = 0; k < 8; k++) {
            float v = tile[row][lane + 32 * k];
            s = fmaf(v, v, s);
        }
        #pragma unroll
        for (int off = 16; off > 0; off >>= 1)
            s += __shfl_down_sync(0xFFFFFFFFu, s, off);
        float invn = 1.0f / fmaxf(sqrtf(__shfl_sync(0xFFFFFFFFu, s, 0)), 1e-12f);

        size_t obase = ((size_t)b * NSP + m0 + row) * KTOT;
        #pragma unroll
        for (int k = 0; k < 8; k++) {
            int c = lane + 32 * k;
            float v = tile[row][c] * invn;
            __nv_bfloat16 hi = __float2bfloat16(v);
            __nv_bfloat16 lo = __float2bfloat16(v - __bfloat162float(hi));
            dst[obase + c] = hi;
            dst[obase + 256 + c] = isP ? lo : hi;
            dst[obase + 512 + c] = isP ? hi : lo;
        }
    }
}

// ---------------------------------------------------------------------------
// Kernel 2: HMMA GEMM (128x128 tile, K=768 bf16) + exp epilogue.
// Warp grid 2(m) x 4(n); warp tile 64x32; mma m16n8k16.
// SMEM tiles: 128 rows x 64 bf16 (128B rows), XOR-swizzled 16B chunks.
// ---------------------------------------------------------------------------
#define SMEM_BUFS  1024
#define SMEM_TOTAL (1024 + 4 * 16384)   // srow/scol + 2 x (A 16KB + B 16KB)

__global__ __launch_bounds__(256, 2)
void gemm_exp_kernel(const float* __restrict__ alpha_p, float* __restrict__ out_e) {
    extern __shared__ char smem[];
    const uint32_t sbase = smem_u32(smem);
    float* srow = (float*)smem;
    float* scol = (float*)(smem + 512);

    const int t = threadIdx.x;
    const int w = t >> 5, lane = t & 31;
    const int b  = blockIdx.z;
    const int i0 = blockIdx.y * 128;
    const int j0 = blockIdx.x * 128;

    if (t < 128) { srow[t] = 0.0f; scol[t] = 0.0f; }

    const __nv_bfloat16* Abase = g_P + ((size_t)b * NSP + i0) * KTOT;
    const __nv_bfloat16* Bbase = g_Q + ((size_t)b * NSP + j0) * KTOT;

    // async-load one 128x64 bf16 chunk of A and B into buffer `buf`
    auto load_chunk = [&](int c, int buf) {
        uint32_t aS = sbase + SMEM_BUFS + buf * 32768;
        uint32_t bS = aS + 16384;
        #pragma unroll
        for (int u = 0; u < 4; u++) {
            int f = t + 256 * u;
            uint32_t row = f >> 3, seg = f & 7;
            uint32_t off = row * 128 + ((seg ^ (row & 7)) << 4);
            cp16(aS + off, Abase + (size_t)row * KTOT + c * 64 + seg * 8);
            cp16(bS + off, Bbase + (size_t)row * KTOT + c * 64 + seg * 8);
        }
    };

    const int wm = w >> 2, wn = w & 3;
    const int r16 = lane & 15, ahi = lane >> 4;
    const int bn  = (lane & 7) + ((lane >> 4) << 3);
    const int bkl = (lane >> 3) & 1;

    float d[4][4][4] = {};

    load_chunk(0, 0);
    cp_commit();

    #pragma unroll 1
    for (int c = 0; c < NCHUNK; c++) {
        if (c < NCHUNK - 1) { load_chunk(c + 1, (c + 1) & 1); cp_commit(); }
        if (c < NCHUNK - 1) cp_wait<1>(); else cp_wait<0>();
        __syncthreads();

        uint32_t aS = sbase + SMEM_BUFS + (c & 1) * 32768;
        uint32_t bS = aS + 16384;

        #pragma unroll
        for (int kk = 0; kk < 4; kk++) {
            uint32_t afr[4][4];
            #pragma unroll
            for (int mt = 0; mt < 4; mt++) {
                uint32_t row = wm * 64 + mt * 16 + r16;
                uint32_t col = (((2 * kk + ahi) ^ (r16 & 7)) << 4);
                ldmx4(afr[mt], aS + row * 128 + col);
            }
            uint32_t bfr[4][2];
            #pragma unroll
            for (int np = 0; np < 2; np++) {
                uint32_t nrow = wn * 32 + np * 16 + bn;
                uint32_t col = (((2 * kk + bkl) ^ (bn & 7)) << 4);
                uint32_t q[4];
                ldmx4(q, bS + nrow * 128 + col);
                bfr[2 * np][0] = q[0]; bfr[2 * np][1] = q[1];
                bfr[2 * np + 1][0] = q[2]; bfr[2 * np + 1][1] = q[3];
            }
            #pragma unroll
            for (int mt = 0; mt < 4; mt++)
                #pragma unroll
                for (int nt = 0; nt < 4; nt++)
                    mma16816(d[mt][nt], afr[mt], bfr[nt]);
        }
        __syncthreads();
    }

    // ---- epilogue: e = exp(alpha * dot); write e; row/col sums ----
    const float alpha = __ldg(alpha_p);
    const int g = lane >> 2, tg = lane & 3;
    float csum[4][2] = {};
    float* outb = out_e + (size_t)b * BN2;

    #pragma unroll
    for (int mt = 0; mt < 4; mt++) {
        float rs0 = 0.0f, rs1 = 0.0f;
        const int row0 = i0 + wm * 64 + mt * 16 + g;
        #pragma unroll
        for (int nt = 0; nt < 4; nt++) {
            float e0 = __expf(d[mt][nt][0] * alpha);
            float e1 = __expf(d[mt][nt][1] * alpha);
            float e2 = __expf(d[mt][nt][2] * alpha);
            float e3 = __expf(d[mt][nt][3] * alpha);
            rs0 += e0 + e1; rs1 += e2 + e3;
            csum[nt][0] += e0 + e2; csum[nt][1] += e1 + e3;
            const int colg = j0 + wn * 32 + nt * 8 + tg * 2;
            *(float2*)(outb + (size_t)row0 * NSP + colg)       = make_float2(e0, e1);
            *(float2*)(outb + (size_t)(row0 + 8) * NSP + colg) = make_float2(e2, e3);
        }
        rs0 += __shfl_xor_sync(0xFFFFFFFFu, rs0, 1);
        rs0 += __shfl_xor_sync(0xFFFFFFFFu, rs0, 2);
        rs1 += __shfl_xor_sync(0xFFFFFFFFu, rs1, 1);
        rs1 += __shfl_xor_sync(0xFFFFFFFFu, rs1, 2);
        if (tg == 0) {
            atomicAdd(&srow[wm * 64 + mt * 16 + g],     rs0);
            atomicAdd(&srow[wm * 64 + mt * 16 + g + 8], rs1);
        }
    }
    #pragma unroll
    for (int nt = 0; nt < 4; nt++)
        #pragma unroll
        for (int cc = 0; cc < 2; cc++) {
            float v = csum[nt][cc];
            v += __shfl_xor_sync(0xFFFFFFFFu, v, 4);
            v += __shfl_xor_sync(0xFFFFFFFFu, v, 8);
            v += __shfl_xor_sync(0xFFFFFFFFu, v, 16);
            if (g == 0) atomicAdd(&scol[wn * 32 + nt * 8 + tg * 2 + cc], v);
        }
    __syncthreads();
    if (t < 128) {
        atomicAdd(&g_rowsum[b * NSP + i0 + t], srow[t]);
        atomicAdd(&g_colsum[b * NSP + j0 + t], scol[t]);
    }
}

// ---------------------------------------------------------------------------
// top-3 helpers
// ---------------------------------------------------------------------------
__device__ __forceinline__ void top3_push(float v, float& v0, float& v1, float& v2) {
    if (v > v2) {
        if (v > v1) {
            v2 = v1;
            if (v > v0) { v1 = v0; v0 = v; } else { v1 = v; }
        } else v2 = v;
    }
}
__device__ __forceinline__ void warp_reduce_top3(float& v0, float& v1, float& v2) {
    #pragma unroll
    for (int off = 16; off > 0; off >>= 1) {
        float u0 = __shfl_down_sync(0xFFFFFFFFu, v0, off);
        float u1 = __shfl_down_sync(0xFFFFFFFFu, v1, off);
        float u2 = __shfl_down_sync(0xFFFFFFFFu, v2, off);
        top3_push(u0, v0, v1, v2);
        top3_push(u1, v0, v1, v2);
        top3_push(u2, v0, v1, v2);
    }
}

// ---------------------------------------------------------------------------
// Kernel 3: row pass. e -> x_c in place; fused row top-3 -> valp.
// ---------------------------------------------------------------------------
__global__ __launch_bounds__(256)
void rowpass_kernel(float* __restrict__ xcq, float* __restrict__ valp) {
    __shared__ float sinvc[NSP];
    const int b = blockIdx.y;
    const int t = threadIdx.x;
    for (int j = t; j < NSP; j += 256)
        sinvc[j] = 1.0f / g_colsum[b * NSP + j];
    __syncthreads();

    const int w = t >> 5, lane = t & 31;
    const int i = blockIdx.x * 8 + w;
    const float invr = 1.0f / g_rowsum[b * NSP + i];
    float* row = xcq + (size_t)b * BN2 + (size_t)i * NSP;

    float v0 = -1e30f, v1 = -1e30f, v2 = -1e30f;
    for (int jb = lane * 4; jb < NSP; jb += 128) {
        float4 e  = *reinterpret_cast<float4*>(row + jb);
        float4 si = *reinterpret_cast<float4*>(&sinvc[jb]);
        float x0 = e.x * e.x * invr * si.x;
        float x1 = e.y * e.y * invr * si.y;
        float x2 = e.z * e.z * invr * si.z;
        float x3 = e.w * e.w * invr * si.w;
        *reinterpret_cast<float4*>(row + jb) = make_float4(x0, x1, x2, x3);
        top3_push(x0, v0, v1, v2);
        top3_push(x1, v0, v1, v2);
        top3_push(x2, v0, v1, v2);
        top3_push(x3, v0, v1, v2);
    }
    warp_reduce_top3(v0, v1, v2);
    if (lane == 0) {
        valp[b * 3 * NSP + 0 * NSP + i] = v0;
        valp[b * 3 * NSP + 1 * NSP + i] = v1;
        valp[b * 3 * NSP + 2 * NSP + i] = v2;
    }
}

// ---------------------------------------------------------------------------
// Kernel 4: column pass. x_c -> x_c^T (xc_o_p) + fused column top-3 -> valq.
// ---------------------------------------------------------------------------
__global__ __launch_bounds__(256)
void colpass_kernel(const float* __restrict__ xcq,
                    float* __restrict__ xcp,
                    float* __restrict__ valq) {
    __shared__ float tile[32][9];
    const int b  = blockIdx.y;
    const int j0 = blockIdx.x << 3;
    const int t  = threadIdx.x;
    const float* src = xcq + (size_t)b * BN2;
    float*       dst = xcp + (size_t)b * BN2;

    const int li = t >> 3, lj = t & 7;
    const int wj = t >> 5, wi = t & 31;

    float v0 = -1e30f, v1 = -1e30f, v2 = -1e30f;
    for (int ic = 0; ic < NSP; ic += 32) {
        tile[li][lj] = src[(size_t)(ic + li) * NSP + j0 + lj];
        __syncthreads();
        float v = tile[wi][wj];
        dst[(size_t)(j0 + wj) * NSP + ic + wi] = v;
        top3_push(v, v0, v1, v2);
        __syncthreads();
    }
    warp_reduce_top3(v0, v1, v2);
    if (wi == 0) {
        int j = j0 + wj;
        valq[b * 3 * NSP + 0 * NSP + j] = v0;
        valq[b * 3 * NSP + 1 * NSP + j] = v1;
        valq[b * 3 * NSP + 2 * NSP + j] = v2;
    }
}

// ---------------------------------------------------------------------------
extern "C" void kernel_launch(void* const* d_in, const int* in_sizes, int n_in,
                              void* d_out, int out_size) {
    const float* xp    = (const float*)d_in[0];
    const float* xq    = (const float*)d_in[1];
    const float* alpha = (const float*)d_in[2];

    float* valp = (float*)d_out;
    float* valq = valp + BATCH * 3 * NSP;
    float* xcp  = valq + BATCH * 3 * NSP;
    float* xcq  = xcp + (size_t)BATCH * BN2;

    // idempotent, called every time (no static guards)
    cudaFuncSetAttribute(gemm_exp_kernel,
                         cudaFuncAttributeMaxDynamicSharedMemorySize, SMEM_TOTAL);

    zero_sums_kernel<<<64, 256>>>();
    prep_kernel<<<dim3(128, BATCH, 2), 256>>>(xp, xq);
    gemm_exp_kernel<<<dim3(32, 32, BATCH), 256, SMEM_TOTAL>>>(alpha, xcq);
    rowpass_kernel<<<dim3(512, BATCH), 256>>>(xcq, valp);
    colpass_kernel<<<dim3(512, BATCH), 256>>>(xcq, xcp, valq);
}